// round 11
// baseline (speedup 1.0000x reference)
#include <cuda_runtime.h>
#include <cuda_bf16.h>
#include <cstdint>

#define BB 2
#define HH 16
#define SS 2048
#define DD 64
#define BH (BB*HH)
#define SCALE 0.125f
#define LOG2E 1.4426950408889634f

static __device__ float g_row_s[BH * SS];
static __device__ __align__(16) uint32_t g_mbits[(size_t)BB * SS * SS / 32];  // 1MB
// bf16 hi/lo scratch (packed bf16x2). K: [bh][key][d], V: [bh][d][key]
static __device__ __align__(16) uint32_t g_kh[(size_t)BH * SS * DD / 2];
static __device__ __align__(16) uint32_t g_kl[(size_t)BH * SS * DD / 2];
static __device__ __align__(16) uint32_t g_vth[(size_t)BH * SS * DD / 2];
static __device__ __align__(16) uint32_t g_vtl[(size_t)BH * SS * DD / 2];

// ---------------------------------------------------------------------------
// helpers
// ---------------------------------------------------------------------------
__device__ __forceinline__ float ex2(float x) {
    float r;
    asm("ex2.approx.f32 %0, %1;" : "=f"(r) : "f"(x));
    return r;
}
__device__ __forceinline__ void pack_hl(float a, float b, uint32_t& h, uint32_t& l) {
    asm("cvt.rn.bf16x2.f32 %0, %1, %2;" : "=r"(h) : "f"(b), "f"(a));
    float ha = __uint_as_float(h << 16);
    float hb = __uint_as_float(h & 0xffff0000u);
    asm("cvt.rn.bf16x2.f32 %0, %1, %2;" : "=r"(l) : "f"(b - hb), "f"(a - ha));
}
__device__ __forceinline__ uint32_t smem_u32(const void* p) {
    uint32_t a;
    asm("{ .reg .u64 t; cvta.to.shared.u64 t, %1; cvt.u32.u64 %0, t; }"
        : "=r"(a) : "l"(p));
    return a;
}
#define CPA16(dst, src) \
    asm volatile("cp.async.cg.shared.global [%0], [%1], 16;" :: "r"(dst), "l"(src))
#define CPA_COMMIT() asm volatile("cp.async.commit_group;" ::: "memory")
#define CPA_WAIT(n)  asm volatile("cp.async.wait_group %0;" :: "n"(n) : "memory")

// mma.sync m16n8k16 row.col f32.bf16.bf16.f32 — D accumulates in place
#define MMA(d, a, b0v, b1v) \
    asm volatile("mma.sync.aligned.m16n8k16.row.col.f32.bf16.bf16.f32 " \
        "{%0,%1,%2,%3}, {%4,%5,%6,%7}, {%8,%9}, {%0,%1,%2,%3};" \
        : "+f"((d)[0]), "+f"((d)[1]), "+f"((d)[2]), "+f"((d)[3]) \
        : "r"((a)[0]), "r"((a)[1]), "r"((a)[2]), "r"((a)[3]), "r"(b0v), "r"(b1v))

// Double-buffered smem: per buffer, K-hi/K-lo/Vt-hi/Vt-lo tiles,
// each [64 rows][64 keys or d] bf16, row stride 144B = 9216 B.
#define B_KH 0
#define B_KL 9216
#define B_VH 18432
#define B_VL 27648
#define BUF_STRIDE 36864
#define SMEM_BYTES (2 * BUF_STRIDE)     // 73728

// ---------------------------------------------------------------------------
// Kernel 0: bit-pack the int32 mask
// ---------------------------------------------------------------------------
__global__ __launch_bounds__(256)
void mask_pack(const int* __restrict__ mask)
{
    const size_t w = (size_t)blockIdx.x * 256 + threadIdx.x;
    const int4* p = (const int4*)mask + w * 8;
    uint32_t bits = 0;
    #pragma unroll
    for (int j = 0; j < 8; j++) {
        int4 x = p[j];
        bits |= (x.x ? 1u : 0u) << (j * 4 + 0);
        bits |= (x.y ? 1u : 0u) << (j * 4 + 1);
        bits |= (x.z ? 1u : 0u) << (j * 4 + 2);
        bits |= (x.w ? 1u : 0u) << (j * 4 + 3);
    }
    g_mbits[w] = bits;
}

// ---------------------------------------------------------------------------
// Kernel 0b: K -> bf16 hi/lo (natural layout). 8 elements per thread.
// ---------------------------------------------------------------------------
__global__ __launch_bounds__(256)
void conv_k(const float* __restrict__ k)
{
    const size_t i0 = ((size_t)blockIdx.x * 256 + threadIdx.x) * 8;
    float4 a = *(const float4*)(k + i0);
    float4 b = *(const float4*)(k + i0 + 4);
    uint32_t h[4], l[4];
    pack_hl(a.x, a.y, h[0], l[0]);
    pack_hl(a.z, a.w, h[1], l[1]);
    pack_hl(b.x, b.y, h[2], l[2]);
    pack_hl(b.z, b.w, h[3], l[3]);
    *(uint4*)(g_kh + i0 / 2) = make_uint4(h[0], h[1], h[2], h[3]);
    *(uint4*)(g_kl + i0 / 2) = make_uint4(l[0], l[1], l[2], l[3]);
}

// ---------------------------------------------------------------------------
// Kernel 0c: V -> bf16 hi/lo transposed [bh][d][key] via smem tile transpose.
// ---------------------------------------------------------------------------
__global__ __launch_bounds__(256)
void conv_vt(const float* __restrict__ v)
{
    __shared__ float ts[64][65];
    const int tid = threadIdx.x;
    const int bh  = blockIdx.y;
    const int n0  = blockIdx.x * 64;

    const int r  = tid >> 2;
    const int c0 = (tid & 3) * 16;
    const float* vp = v + ((size_t)bh * SS + n0 + r) * DD + c0;
    #pragma unroll
    for (int i = 0; i < 4; i++) {
        float4 f = *(const float4*)(vp + i * 4);
        ts[r][c0 + i*4 + 0] = f.x;
        ts[r][c0 + i*4 + 1] = f.y;
        ts[r][c0 + i*4 + 2] = f.z;
        ts[r][c0 + i*4 + 3] = f.w;
    }
    __syncthreads();

    const int d  = tid >> 2;
    const int kc = (tid & 3) * 16;
    uint32_t h[8], l[8];
    #pragma unroll
    for (int m = 0; m < 8; m++)
        pack_hl(ts[kc + 2*m][d], ts[kc + 2*m + 1][d], h[m], l[m]);
    const size_t o = (((size_t)bh * DD + d) * SS + n0 + kc) / 2;
    *(uint4*)(g_vth + o)     = make_uint4(h[0], h[1], h[2], h[3]);
    *(uint4*)(g_vth + o + 4) = make_uint4(h[4], h[5], h[6], h[7]);
    *(uint4*)(g_vtl + o)     = make_uint4(l[0], l[1], l[2], l[3]);
    *(uint4*)(g_vtl + o + 4) = make_uint4(l[4], l[5], l[6], l[7]);
}

// ---------------------------------------------------------------------------
// Q fragments (hi/lo), scale*log2e folded in
// ---------------------------------------------------------------------------
__device__ __forceinline__ void load_q_frags(const float* __restrict__ q,
                                             int bh, int r0, int r8, int t,
                                             uint32_t (&qh)[4][4], uint32_t (&ql)[4][4])
{
    const float* qp = q + (size_t)bh * SS * DD;
    const float sc = SCALE * LOG2E;
    #pragma unroll
    for (int ks = 0; ks < 4; ks++) {
        const int c = ks * 16 + t * 2;
        float2 x0 = *(const float2*)(qp + (size_t)r0 * DD + c);
        float2 x1 = *(const float2*)(qp + (size_t)r8 * DD + c);
        float2 x2 = *(const float2*)(qp + (size_t)r0 * DD + c + 8);
        float2 x3 = *(const float2*)(qp + (size_t)r8 * DD + c + 8);
        pack_hl(x0.x * sc, x0.y * sc, qh[ks][0], ql[ks][0]);
        pack_hl(x1.x * sc, x1.y * sc, qh[ks][1], ql[ks][1]);
        pack_hl(x2.x * sc, x2.y * sc, qh[ks][2], ql[ks][2]);
        pack_hl(x3.x * sc, x3.y * sc, qh[ks][3], ql[ks][3]);
    }
}

// ---------------------------------------------------------------------------
// stage one 64-key tile (K hi/lo + Vt hi/lo) into buffer via cp.async
// ---------------------------------------------------------------------------
__device__ __forceinline__ void stage_tile(uint32_t sbuf,
                                           const char* kh_b, const char* kl_b,
                                           const char* vh_b, const char* vl_b,
                                           int n0, int tid)
{
    #pragma unroll
    for (int cc = 0; cc < 2; cc++) {
        const int c   = tid + cc * 256;      // 0..511
        const int r   = c >> 3;              // 0..63 (key for K, d for V)
        const int col = c & 7;               // 16B chunk within 128B row
        const size_t ksrc = (size_t)(n0 + r) * (DD * 2) + col * 16;
        const size_t vsrc = ((size_t)r * SS + n0) * 2 + col * 16;
        const uint32_t dst = r * 144 + col * 16;
        CPA16(sbuf + B_KH + dst, kh_b + ksrc);
        CPA16(sbuf + B_KL + dst, kl_b + ksrc);
        CPA16(sbuf + B_VH + dst, vh_b + vsrc);
        CPA16(sbuf + B_VL + dst, vl_b + vsrc);
    }
}

// ---------------------------------------------------------------------------
// Kernel 1: flash, double-buffered 64-key tiles.
// ---------------------------------------------------------------------------
__global__ void __launch_bounds__(256, 2)
sdpa_flash(const float* __restrict__ q,
           float* __restrict__ atten, float* __restrict__ out)
{
    extern __shared__ char smem[];
    const int tid  = threadIdx.x;
    const int lane = tid & 31;
    const int g    = lane >> 2;
    const int t    = lane & 3;
    const int w    = tid >> 5;
    const int bh   = blockIdx.y;
    const int b    = bh / HH;
    const int q0   = blockIdx.x * 128;
    const int r0   = q0 + w * 16 + g;
    const int r8   = r0 + 8;
    const uint32_t sb = smem_u32(smem);

    const size_t mb0 = ((size_t)b * SS + r0) * 64;
    const size_t mb8 = ((size_t)b * SS + r8) * 64;
    float* arow_g  = atten + ((size_t)bh * SS + r0) * SS;
    float* arow_g8 = atten + ((size_t)bh * SS + r8) * SS;

    const char* kh_b = (const char*)g_kh  + (size_t)bh * SS * DD * 2;
    const char* kl_b = (const char*)g_kl  + (size_t)bh * SS * DD * 2;
    const char* vh_b = (const char*)g_vth + (size_t)bh * SS * DD * 2;
    const char* vl_b = (const char*)g_vtl + (size_t)bh * SS * DD * 2;

    // prologue: stage tile 0, overlap q-fragment loads with it
    stage_tile(sb, kh_b, kl_b, vh_b, vl_b, 0, tid);
    CPA_COMMIT();

    uint32_t qh[4][4], ql[4][4];
    load_q_frags(q, bh, r0, r8, t, qh, ql);

    float sum_g = 0.0f, sum_g8 = 0.0f;
    float o[8][4];
    #pragma unroll
    for (int nd = 0; nd < 8; nd++)
        #pragma unroll
        for (int i = 0; i < 4; i++) o[nd][i] = 0.0f;

    #pragma unroll 1
    for (int kt = 0; kt < 32; kt++) {
        const int n0  = kt * 64;
        const int cur = kt & 1;
        const char* bufc = smem + cur * BUF_STRIDE;

        // prefetch next tile into other buffer (its last readers synced below)
        if (kt + 1 < 32) {
            stage_tile(sb + (cur ^ 1) * BUF_STRIDE, kh_b, kl_b, vh_b, vl_b,
                       (kt + 1) * 64, tid);
            CPA_COMMIT();
            CPA_WAIT(1);           // tile kt complete, kt+1 in flight
        } else {
            CPA_WAIT(0);
        }
        __syncthreads();

        // ---- QK for 64 keys ----
        float s[8][4];
        #pragma unroll
        for (int nt = 0; nt < 8; nt++)
            #pragma unroll
            for (int i = 0; i < 4; i++) s[nt][i] = 0.0f;

        #pragma unroll
        for (int ks = 0; ks < 4; ks++) {
            #pragma unroll
            for (int pass = 0; pass < 3; pass++) {
                const uint32_t* A = (pass == 2) ? ql[ks] : qh[ks];
                const int bb = (pass == 1) ? B_KL : B_KH;
                #pragma unroll
                for (int nt = 0; nt < 8; nt++) {
                    const char* ad = bufc + bb + (nt * 8 + g) * 144 + ks * 32 + t * 4;
                    uint32_t b0 = *(const uint32_t*)ad;
                    uint32_t b1 = *(const uint32_t*)(ad + 16);
                    MMA(s[nt], A, b0, b1);
                }
            }
        }

        // ---- epilogue + AV ----
        const uint2 mg = *(const uint2*)(g_mbits + mb0 + kt * 2);
        const uint2 m8 = *(const uint2*)(g_mbits + mb8 + kt * 2);

        #pragma unroll
        for (int kap = 0; kap < 4; kap++) {
            uint32_t ah[4], al[4];
            #pragma unroll
            for (int i = 0; i < 2; i++) {
                const int nt = kap * 2 + i;
                const uint32_t wg = ((nt & 4) ? mg.y : mg.x) >> ((nt & 3) * 8 + t * 2);
                const uint32_t w8 = ((nt & 4) ? m8.y : m8.x) >> ((nt & 3) * 8 + t * 2);
                const float e0 = (wg      & 1) ? 0.0f : ex2(s[nt][0]);
                const float e1 = (wg >> 1 & 1) ? 0.0f : ex2(s[nt][1]);
                const float e2 = (w8      & 1) ? 0.0f : ex2(s[nt][2]);
                const float e3 = (w8 >> 1 & 1) ? 0.0f : ex2(s[nt][3]);
                sum_g  += e0 + e1;
                sum_g8 += e2 + e3;
                const int c = n0 + nt * 8 + t * 2;
                __stcs((float2*)(arow_g  + c), make_float2(e0, e1));
                __stcs((float2*)(arow_g8 + c), make_float2(e2, e3));
                pack_hl(e0, e1, ah[i*2+0], al[i*2+0]);
                pack_hl(e2, e3, ah[i*2+1], al[i*2+1]);
            }
            #pragma unroll
            for (int nd = 0; nd < 8; nd++) {
                const int vbase = (nd * 8 + g) * 144 + kap * 32 + t * 4;
                const char* vh = bufc + B_VH + vbase;
                const char* vl = bufc + B_VL + vbase;
                uint32_t bh0 = *(const uint32_t*)vh;
                uint32_t bh1 = *(const uint32_t*)(vh + 16);
                uint32_t bl0 = *(const uint32_t*)vl;
                uint32_t bl1 = *(const uint32_t*)(vl + 16);
                MMA(o[nd], ah, bh0, bh1);
                MMA(o[nd], ah, bl0, bl1);
                MMA(o[nd], al, bh0, bh1);
            }
        }
        __syncthreads();   // all reads of bufc done before it is re-staged
    }

    sum_g  += __shfl_xor_sync(0xffffffffu, sum_g, 1);
    sum_g  += __shfl_xor_sync(0xffffffffu, sum_g, 2);
    sum_g8 += __shfl_xor_sync(0xffffffffu, sum_g8, 1);
    sum_g8 += __shfl_xor_sync(0xffffffffu, sum_g8, 2);
    const float inv_g  = 1.0f / sum_g;
    const float inv_g8 = 1.0f / sum_g8;
    if (t == 0) {
        g_row_s[bh * SS + r0] = sum_g;
        g_row_s[bh * SS + r8] = sum_g8;
    }

    float* orow_g  = out + ((size_t)bh * SS + r0) * DD;
    float* orow_g8 = out + ((size_t)bh * SS + r8) * DD;
    #pragma unroll
    for (int nd = 0; nd < 8; nd++) {
        *(float2*)(orow_g  + nd * 8 + t * 2) = make_float2(o[nd][0] * inv_g,  o[nd][1] * inv_g);
        *(float2*)(orow_g8 + nd * 8 + t * 2) = make_float2(o[nd][2] * inv_g8, o[nd][3] * inv_g8);
    }
}

// ---------------------------------------------------------------------------
// Kernel 2: atten[row, :] *= 1/g_row_s[row]
// ---------------------------------------------------------------------------
__global__ void __launch_bounds__(256)
atten_norm(float* __restrict__ atten)
{
    const int row = blockIdx.x;
    const float inv = 1.0f / g_row_s[row];
    float4* p = (float4*)(atten + (size_t)row * SS);
    const int i0 = threadIdx.x;
    float4 a = __ldcs(p + i0);
    float4 c = __ldcs(p + i0 + 256);
    a.x *= inv; a.y *= inv; a.z *= inv; a.w *= inv;
    c.x *= inv; c.y *= inv; c.z *= inv; c.w *= inv;
    __stcs(p + i0, a);
    __stcs(p + i0 + 256, c);
}

// ---------------------------------------------------------------------------
extern "C" void kernel_launch(void* const* d_in, const int* in_sizes, int n_in,
                              void* d_out, int out_size)
{
    const float* q = (const float*)d_in[0];
    const float* k = (const float*)d_in[1];
    const float* v = (const float*)d_in[2];
    const int*   mask = (const int*)d_in[3];

    float* out   = (float*)d_out;                 // [B,H,S,D]
    float* atten = out + (size_t)BH * SS * DD;    // [B,H,S,S]

    cudaFuncSetAttribute(sdpa_flash, cudaFuncAttributeMaxDynamicSharedMemorySize, SMEM_BYTES);

    mask_pack<<<1024, 256>>>(mask);
    conv_k<<<BH * SS * DD / (256 * 8), 256>>>(k);
    conv_vt<<<dim3(SS / 64, BH), 256>>>(v);
    dim3 grid(SS / 128, BH);
    sdpa_flash<<<grid, 256, SMEM_BYTES>>>(q, atten, out);
    atten_norm<<<BH * SS, 256>>>(atten);
    (void)in_sizes; (void)n_in; (void)out_size;
}

// round 12
// speedup vs baseline: 1.4730x; 1.4730x over previous
#include <cuda_runtime.h>
#include <cuda_bf16.h>
#include <cstdint>

#define BB 2
#define HH 16
#define SS 2048
#define DD 64
#define BH (BB*HH)
#define SCALE 0.125f
#define LOG2E 1.4426950408889634f

static __device__ float g_row_s[BH * SS];
static __device__ __align__(16) uint32_t g_mbits[(size_t)BB * SS * SS / 32];  // 1MB
// bf16 hi/lo scratch (packed bf16x2), PAIR-PERMUTED [0,4,1,5,2,6,3,7] within
// each 32B group. K: [bh][key][d], V: [bh][d][key]
static __device__ __align__(16) uint32_t g_kh[(size_t)BH * SS * DD / 2];
static __device__ __align__(16) uint32_t g_kl[(size_t)BH * SS * DD / 2];
static __device__ __align__(16) uint32_t g_vth[(size_t)BH * SS * DD / 2];
static __device__ __align__(16) uint32_t g_vtl[(size_t)BH * SS * DD / 2];

// ---------------------------------------------------------------------------
// helpers
// ---------------------------------------------------------------------------
__device__ __forceinline__ float ex2(float x) {
    float r;
    asm("ex2.approx.f32 %0, %1;" : "=f"(r) : "f"(x));
    return r;
}
__device__ __forceinline__ void pack_hl(float a, float b, uint32_t& h, uint32_t& l) {
    asm("cvt.rn.bf16x2.f32 %0, %1, %2;" : "=r"(h) : "f"(b), "f"(a));
    float ha = __uint_as_float(h << 16);
    float hb = __uint_as_float(h & 0xffff0000u);
    asm("cvt.rn.bf16x2.f32 %0, %1, %2;" : "=r"(l) : "f"(b - hb), "f"(a - ha));
}
__device__ __forceinline__ uint32_t smem_u32(const void* p) {
    uint32_t a;
    asm("{ .reg .u64 t; cvta.to.shared.u64 t, %1; cvt.u32.u64 %0, t; }"
        : "=r"(a) : "l"(p));
    return a;
}
#define CPA16(dst, src) \
    asm volatile("cp.async.cg.shared.global [%0], [%1], 16;" :: "r"(dst), "l"(src))
#define CPA_COMMIT() asm volatile("cp.async.commit_group;" ::: "memory")
#define CPA_WAIT0()  asm volatile("cp.async.wait_group 0;" ::: "memory")

// mma.sync m16n8k16 row.col f32.bf16.bf16.f32 — D accumulates in place
#define MMA(d, a, b0v, b1v) \
    asm volatile("mma.sync.aligned.m16n8k16.row.col.f32.bf16.bf16.f32 " \
        "{%0,%1,%2,%3}, {%4,%5,%6,%7}, {%8,%9}, {%0,%1,%2,%3};" \
        : "+f"((d)[0]), "+f"((d)[1]), "+f"((d)[2]), "+f"((d)[3]) \
        : "r"((a)[0]), "r"((a)[1]), "r"((a)[2]), "r"((a)[3]), "r"(b0v), "r"(b1v))

// smem: K tiles [key 128][d 64] bf16, row stride 160B (128B data + 32 pad).
//       V tiles [d 64][key 128] bf16, row stride 288B (256B data + 32 pad).
#define SM_KH 0
#define SM_KL 20480
#define SM_VH 40960
#define SM_VL 59392
#define SMEM_BYTES 77824

// ---------------------------------------------------------------------------
// Kernel 0: bit-pack the int32 mask
// ---------------------------------------------------------------------------
__global__ __launch_bounds__(256)
void mask_pack(const int* __restrict__ mask)
{
    const size_t w = (size_t)blockIdx.x * 256 + threadIdx.x;
    const int4* p = (const int4*)mask + w * 8;
    uint32_t bits = 0;
    #pragma unroll
    for (int j = 0; j < 8; j++) {
        int4 x = p[j];
        bits |= (x.x ? 1u : 0u) << (j * 4 + 0);
        bits |= (x.y ? 1u : 0u) << (j * 4 + 1);
        bits |= (x.z ? 1u : 0u) << (j * 4 + 2);
        bits |= (x.w ? 1u : 0u) << (j * 4 + 3);
    }
    g_mbits[w] = bits;
}

// ---------------------------------------------------------------------------
// Kernel 0b: K -> bf16 hi/lo, pair-permuted within each 32B (8-pair) group.
// One thread = one group of 16 consecutive d (8 bf16x2 pairs).
// ---------------------------------------------------------------------------
__global__ __launch_bounds__(256)
void conv_k(const float* __restrict__ k)
{
    const size_t gi = (size_t)blockIdx.x * 256 + threadIdx.x;   // group index
    const float* kp = k + gi * 16;
    uint32_t h[8], l[8];
    #pragma unroll
    for (int i = 0; i < 4; i++) {
        float4 f = *(const float4*)(kp + i * 4);
        pack_hl(f.x, f.y, h[i*2+0], l[i*2+0]);
        pack_hl(f.z, f.w, h[i*2+1], l[i*2+1]);
    }
    // permuted order [0,4,1,5,2,6,3,7]
    *(uint4*)(g_kh + gi * 8)     = make_uint4(h[0], h[4], h[1], h[5]);
    *(uint4*)(g_kh + gi * 8 + 4) = make_uint4(h[2], h[6], h[3], h[7]);
    *(uint4*)(g_kl + gi * 8)     = make_uint4(l[0], l[4], l[1], l[5]);
    *(uint4*)(g_kl + gi * 8 + 4) = make_uint4(l[2], l[6], l[3], l[7]);
}

// ---------------------------------------------------------------------------
// Kernel 0c: V -> bf16 hi/lo transposed [bh][d][key], pair-permuted per group.
// ---------------------------------------------------------------------------
__global__ __launch_bounds__(256)
void conv_vt(const float* __restrict__ v)
{
    __shared__ float ts[64][65];
    const int tid = threadIdx.x;
    const int bh  = blockIdx.y;
    const int n0  = blockIdx.x * 64;

    const int r  = tid >> 2;
    const int c0 = (tid & 3) * 16;
    const float* vp = v + ((size_t)bh * SS + n0 + r) * DD + c0;
    #pragma unroll
    for (int i = 0; i < 4; i++) {
        float4 f = *(const float4*)(vp + i * 4);
        ts[r][c0 + i*4 + 0] = f.x;
        ts[r][c0 + i*4 + 1] = f.y;
        ts[r][c0 + i*4 + 2] = f.z;
        ts[r][c0 + i*4 + 3] = f.w;
    }
    __syncthreads();

    const int d  = tid >> 2;
    const int kc = (tid & 3) * 16;     // one 8-pair group of keys
    uint32_t h[8], l[8];
    #pragma unroll
    for (int m = 0; m < 8; m++)
        pack_hl(ts[kc + 2*m][d], ts[kc + 2*m + 1][d], h[m], l[m]);
    const size_t o = (((size_t)bh * DD + d) * SS + n0 + kc) / 2;
    *(uint4*)(g_vth + o)     = make_uint4(h[0], h[4], h[1], h[5]);
    *(uint4*)(g_vth + o + 4) = make_uint4(h[2], h[6], h[3], h[7]);
    *(uint4*)(g_vtl + o)     = make_uint4(l[0], l[4], l[1], l[5]);
    *(uint4*)(g_vtl + o + 4) = make_uint4(l[2], l[6], l[3], l[7]);
}

// ---------------------------------------------------------------------------
// Q fragments (hi/lo), scale*log2e folded in
// ---------------------------------------------------------------------------
__device__ __forceinline__ void load_q_frags(const float* __restrict__ q,
                                             int bh, int r0, int r8, int t,
                                             uint32_t (&qh)[4][4], uint32_t (&ql)[4][4])
{
    const float* qp = q + (size_t)bh * SS * DD;
    const float sc = SCALE * LOG2E;
    #pragma unroll
    for (int ks = 0; ks < 4; ks++) {
        const int c = ks * 16 + t * 2;
        float2 x0 = *(const float2*)(qp + (size_t)r0 * DD + c);
        float2 x1 = *(const float2*)(qp + (size_t)r8 * DD + c);
        float2 x2 = *(const float2*)(qp + (size_t)r0 * DD + c + 8);
        float2 x3 = *(const float2*)(qp + (size_t)r8 * DD + c + 8);
        pack_hl(x0.x * sc, x0.y * sc, qh[ks][0], ql[ks][0]);
        pack_hl(x1.x * sc, x1.y * sc, qh[ks][1], ql[ks][1]);
        pack_hl(x2.x * sc, x2.y * sc, qh[ks][2], ql[ks][2]);
        pack_hl(x3.x * sc, x3.y * sc, qh[ks][3], ql[ks][3]);
    }
}

// ---------------------------------------------------------------------------
// Kernel 1: flash, R10 structure (128-key tiles, single buffer), LDS.64 reads.
// ---------------------------------------------------------------------------
__global__ void __launch_bounds__(256, 2)
sdpa_flash(const float* __restrict__ q,
           float* __restrict__ atten, float* __restrict__ out)
{
    extern __shared__ char smem[];
    const int tid  = threadIdx.x;
    const int lane = tid & 31;
    const int g    = lane >> 2;
    const int t    = lane & 3;
    const int w    = tid >> 5;
    const int bh   = blockIdx.y;
    const int b    = bh / HH;
    const int q0   = blockIdx.x * 128;
    const int r0   = q0 + w * 16 + g;
    const int r8   = r0 + 8;
    const uint32_t sb = smem_u32(smem);

    const size_t mb0 = ((size_t)b * SS + r0) * 64;
    const size_t mb8 = ((size_t)b * SS + r8) * 64;
    float* arow_g  = atten + ((size_t)bh * SS + r0) * SS;
    float* arow_g8 = atten + ((size_t)bh * SS + r8) * SS;

    uint32_t qh[4][4], ql[4][4];
    load_q_frags(q, bh, r0, r8, t, qh, ql);

    float sum_g = 0.0f, sum_g8 = 0.0f;
    float o[8][4];
    #pragma unroll
    for (int nd = 0; nd < 8; nd++)
        #pragma unroll
        for (int i = 0; i < 4; i++) o[nd][i] = 0.0f;

    const char* kh_b = (const char*)g_kh  + (size_t)bh * SS * DD * 2;
    const char* kl_b = (const char*)g_kl  + (size_t)bh * SS * DD * 2;
    const char* vh_b = (const char*)g_vth + (size_t)bh * SS * DD * 2;
    const char* vl_b = (const char*)g_vtl + (size_t)bh * SS * DD * 2;

    for (int kt = 0; kt < 16; kt++) {
        const int n0 = kt * 128;
        __syncthreads();   // previous compute done with smem
        #pragma unroll
        for (int cc = 0; cc < 4; cc++) {
            const int c = tid + cc * 256;
            const int kr = c >> 3, kc = c & 7;          // K chunk (128 rows x 8)
            const int vd = c >> 4, vc = c & 15;         // V chunk (64 rows x 16)
            const size_t ksrc = ((size_t)(n0 + kr) * DD) * 2 + kc * 16;
            const size_t vsrc = ((size_t)vd * SS + n0) * 2 + vc * 16;
            CPA16(sb + SM_KH + kr * 160 + kc * 16, kh_b + ksrc);
            CPA16(sb + SM_KL + kr * 160 + kc * 16, kl_b + ksrc);
            CPA16(sb + SM_VH + vd * 288 + vc * 16, vh_b + vsrc);
            CPA16(sb + SM_VL + vd * 288 + vc * 16, vl_b + vsrc);
        }
        CPA_COMMIT();
        CPA_WAIT0();
        __syncthreads();

        uint4 mg = *(const uint4*)(g_mbits + mb0 + n0 / 32);
        uint4 m8 = *(const uint4*)(g_mbits + mb8 + n0 / 32);
        const uint32_t* mgw = (const uint32_t*)&mg;
        const uint32_t* m8w = (const uint32_t*)&m8;

        #pragma unroll
        for (int h = 0; h < 2; h++) {
            float s[8][4];
            #pragma unroll
            for (int nt = 0; nt < 8; nt++)
                #pragma unroll
                for (int i = 0; i < 4; i++) s[nt][i] = 0.0f;

            #pragma unroll
            for (int ks = 0; ks < 4; ks++) {
                #pragma unroll
                for (int pass = 0; pass < 3; pass++) {
                    const uint32_t* A = (pass == 2) ? ql[ks] : qh[ks];
                    const int bb = (pass == 1) ? SM_KL : SM_KH;
                    #pragma unroll
                    for (int nt = 0; nt < 8; nt++) {
                        const char* ad = smem + bb + ((h * 8 + nt) * 8 + g) * 160
                                       + ks * 32 + t * 8;
                        uint2 b01 = *(const uint2*)ad;     // LDS.64: pairs (p, p+4)
                        MMA(s[nt], A, b01.x, b01.y);
                    }
                }
            }

            #pragma unroll
            for (int kap = 0; kap < 4; kap++) {
                uint32_t ah[4], al[4];
                #pragma unroll
                for (int i = 0; i < 2; i++) {
                    const int nt  = kap * 2 + i;
                    const int ntg = h * 8 + nt;
                    const uint32_t wg = mgw[ntg >> 2] >> ((ntg & 3) * 8 + t * 2);
                    const uint32_t w8 = m8w[ntg >> 2] >> ((ntg & 3) * 8 + t * 2);
                    const float e0 = (wg      & 1) ? 0.0f : ex2(s[nt][0]);
                    const float e1 = (wg >> 1 & 1) ? 0.0f : ex2(s[nt][1]);
                    const float e2 = (w8      & 1) ? 0.0f : ex2(s[nt][2]);
                    const float e3 = (w8 >> 1 & 1) ? 0.0f : ex2(s[nt][3]);
                    sum_g  += e0 + e1;
                    sum_g8 += e2 + e3;
                    const int c = n0 + ntg * 8 + t * 2;
                    __stcs((float2*)(arow_g  + c), make_float2(e0, e1));
                    __stcs((float2*)(arow_g8 + c), make_float2(e2, e3));
                    pack_hl(e0, e1, ah[i*2+0], al[i*2+0]);
                    pack_hl(e2, e3, ah[i*2+1], al[i*2+1]);
                }
                #pragma unroll
                for (int nd = 0; nd < 8; nd++) {
                    const int vbase = (nd * 8 + g) * 288 + (h * 4 + kap) * 32 + t * 8;
                    uint2 vh2 = *(const uint2*)(smem + SM_VH + vbase);   // LDS.64
                    uint2 vl2 = *(const uint2*)(smem + SM_VL + vbase);   // LDS.64
                    MMA(o[nd], ah, vh2.x, vh2.y);
                    MMA(o[nd], ah, vl2.x, vl2.y);
                    MMA(o[nd], al, vh2.x, vh2.y);
                }
            }
        }
    }

    sum_g  += __shfl_xor_sync(0xffffffffu, sum_g, 1);
    sum_g  += __shfl_xor_sync(0xffffffffu, sum_g, 2);
    sum_g8 += __shfl_xor_sync(0xffffffffu, sum_g8, 1);
    sum_g8 += __shfl_xor_sync(0xffffffffu, sum_g8, 2);
    const float inv_g  = 1.0f / sum_g;
    const float inv_g8 = 1.0f / sum_g8;
    if (t == 0) {
        g_row_s[bh * SS + r0] = sum_g;
        g_row_s[bh * SS + r8] = sum_g8;
    }

    float* orow_g  = out + ((size_t)bh * SS + r0) * DD;
    float* orow_g8 = out + ((size_t)bh * SS + r8) * DD;
    #pragma unroll
    for (int nd = 0; nd < 8; nd++) {
        *(float2*)(orow_g  + nd * 8 + t * 2) = make_float2(o[nd][0] * inv_g,  o[nd][1] * inv_g);
        *(float2*)(orow_g8 + nd * 8 + t * 2) = make_float2(o[nd][2] * inv_g8, o[nd][3] * inv_g8);
    }
}

// ---------------------------------------------------------------------------
// Kernel 2: atten[row, :] *= 1/g_row_s[row]
// ---------------------------------------------------------------------------
__global__ void __launch_bounds__(256)
atten_norm(float* __restrict__ atten)
{
    const int row = blockIdx.x;
    const float inv = 1.0f / g_row_s[row];
    float4* p = (float4*)(atten + (size_t)row * SS);
    const int i0 = threadIdx.x;
    float4 a = __ldcs(p + i0);
    float4 c = __ldcs(p + i0 + 256);
    a.x *= inv; a.y *= inv; a.z *= inv; a.w *= inv;
    c.x *= inv; c.y *= inv; c.z *= inv; c.w *= inv;
    __stcs(p + i0, a);
    __stcs(p + i0 + 256, c);
}

// ---------------------------------------------------------------------------
extern "C" void kernel_launch(void* const* d_in, const int* in_sizes, int n_in,
                              void* d_out, int out_size)
{
    const float* q = (const float*)d_in[0];
    const float* k = (const float*)d_in[1];
    const float* v = (const float*)d_in[2];
    const int*   mask = (const int*)d_in[3];

    float* out   = (float*)d_out;                 // [B,H,S,D]
    float* atten = out + (size_t)BH * SS * DD;    // [B,H,S,S]

    cudaFuncSetAttribute(sdpa_flash, cudaFuncAttributeMaxDynamicSharedMemorySize, SMEM_BYTES);

    mask_pack<<<1024, 256>>>(mask);
    conv_k<<<BH * SS * DD / (256 * 16), 256>>>(k);
    conv_vt<<<dim3(SS / 64, BH), 256>>>(v);
    dim3 grid(SS / 128, BH);
    sdpa_flash<<<grid, 256, SMEM_BYTES>>>(q, atten, out);
    atten_norm<<<BH * SS, 256>>>(atten);
    (void)in_sizes; (void)n_in; (void)out_size;
}

// round 13
// speedup vs baseline: 1.5103x; 1.0253x over previous
#include <cuda_runtime.h>
#include <cuda_bf16.h>
#include <cstdint>

#define BB 2
#define HH 16
#define SS 2048
#define DD 64
#define BH (BB*HH)
#define SCALE 0.125f
#define LOG2E 1.4426950408889634f

static __device__ float g_row_s[BH * SS];
static __device__ __align__(16) uint32_t g_mbits[(size_t)BB * SS * SS / 32];  // 1MB
// bf16 hi/lo scratch (packed bf16x2), PAIR-PERMUTED [0,4,1,5,2,6,3,7] within
// each 32B group. K: [bh][key][d], V: [bh][d][key]
static __device__ __align__(16) uint32_t g_kh[(size_t)BH * SS * DD / 2];
static __device__ __align__(16) uint32_t g_kl[(size_t)BH * SS * DD / 2];
static __device__ __align__(16) uint32_t g_vth[(size_t)BH * SS * DD / 2];
static __device__ __align__(16) uint32_t g_vtl[(size_t)BH * SS * DD / 2];

// ---------------------------------------------------------------------------
// helpers
// ---------------------------------------------------------------------------
__device__ __forceinline__ float ex2(float x) {
    float r;
    asm("ex2.approx.f32 %0, %1;" : "=f"(r) : "f"(x));
    return r;
}
__device__ __forceinline__ void pack_hl(float a, float b, uint32_t& h, uint32_t& l) {
    asm("cvt.rn.bf16x2.f32 %0, %1, %2;" : "=r"(h) : "f"(b), "f"(a));
    float ha = __uint_as_float(h << 16);
    float hb = __uint_as_float(h & 0xffff0000u);
    asm("cvt.rn.bf16x2.f32 %0, %1, %2;" : "=r"(l) : "f"(b - hb), "f"(a - ha));
}
__device__ __forceinline__ uint32_t smem_u32(const void* p) {
    uint32_t a;
    asm("{ .reg .u64 t; cvta.to.shared.u64 t, %1; cvt.u32.u64 %0, t; }"
        : "=r"(a) : "l"(p));
    return a;
}
#define CPA16(dst, src) \
    asm volatile("cp.async.cg.shared.global [%0], [%1], 16;" :: "r"(dst), "l"(src))
#define CPA_COMMIT() asm volatile("cp.async.commit_group;" ::: "memory")
#define CPA_WAIT(n)  asm volatile("cp.async.wait_group %0;" :: "n"(n) : "memory")

// mma.sync m16n8k16 row.col f32.bf16.bf16.f32 — D accumulates in place
#define MMA(d, a, b0v, b1v) \
    asm volatile("mma.sync.aligned.m16n8k16.row.col.f32.bf16.bf16.f32 " \
        "{%0,%1,%2,%3}, {%4,%5,%6,%7}, {%8,%9}, {%0,%1,%2,%3};" \
        : "+f"((d)[0]), "+f"((d)[1]), "+f"((d)[2]), "+f"((d)[3]) \
        : "r"((a)[0]), "r"((a)[1]), "r"((a)[2]), "r"((a)[3]), "r"(b0v), "r"(b1v))

// Pass A smem: double-buffered K tiles [key 128][d 64] bf16, row stride 160B.
#define A_KH 0
#define A_KL 20480
#define A_BUF 40960
#define SMEM_A (2 * A_BUF)          // 81920

// Pass B smem: double-buffered V tiles [d 64][key 128] bf16, row stride 288B.
#define B_VH 0
#define B_VL 18432
#define B_BUF 36864
#define SMEM_B (2 * B_BUF)          // 73728

// ---------------------------------------------------------------------------
// Kernel 0: bit-pack the int32 mask
// ---------------------------------------------------------------------------
__global__ __launch_bounds__(256)
void mask_pack(const int* __restrict__ mask)
{
    const size_t w = (size_t)blockIdx.x * 256 + threadIdx.x;
    const int4* p = (const int4*)mask + w * 8;
    uint32_t bits = 0;
    #pragma unroll
    for (int j = 0; j < 8; j++) {
        int4 x = p[j];
        bits |= (x.x ? 1u : 0u) << (j * 4 + 0);
        bits |= (x.y ? 1u : 0u) << (j * 4 + 1);
        bits |= (x.z ? 1u : 0u) << (j * 4 + 2);
        bits |= (x.w ? 1u : 0u) << (j * 4 + 3);
    }
    g_mbits[w] = bits;
}

// ---------------------------------------------------------------------------
// Kernel 0b: K -> bf16 hi/lo, pair-permuted within each 32B (8-pair) group.
// ---------------------------------------------------------------------------
__global__ __launch_bounds__(256)
void conv_k(const float* __restrict__ k)
{
    const size_t gi = (size_t)blockIdx.x * 256 + threadIdx.x;
    const float* kp = k + gi * 16;
    uint32_t h[8], l[8];
    #pragma unroll
    for (int i = 0; i < 4; i++) {
        float4 f = *(const float4*)(kp + i * 4);
        pack_hl(f.x, f.y, h[i*2+0], l[i*2+0]);
        pack_hl(f.z, f.w, h[i*2+1], l[i*2+1]);
    }
    *(uint4*)(g_kh + gi * 8)     = make_uint4(h[0], h[4], h[1], h[5]);
    *(uint4*)(g_kh + gi * 8 + 4) = make_uint4(h[2], h[6], h[3], h[7]);
    *(uint4*)(g_kl + gi * 8)     = make_uint4(l[0], l[4], l[1], l[5]);
    *(uint4*)(g_kl + gi * 8 + 4) = make_uint4(l[2], l[6], l[3], l[7]);
}

// ---------------------------------------------------------------------------
// Kernel 0c: V -> bf16 hi/lo transposed [bh][d][key], pair-permuted per group.
// ---------------------------------------------------------------------------
__global__ __launch_bounds__(256)
void conv_vt(const float* __restrict__ v)
{
    __shared__ float ts[64][65];
    const int tid = threadIdx.x;
    const int bh  = blockIdx.y;
    const int n0  = blockIdx.x * 64;

    const int r  = tid >> 2;
    const int c0 = (tid & 3) * 16;
    const float* vp = v + ((size_t)bh * SS + n0 + r) * DD + c0;
    #pragma unroll
    for (int i = 0; i < 4; i++) {
        float4 f = *(const float4*)(vp + i * 4);
        ts[r][c0 + i*4 + 0] = f.x;
        ts[r][c0 + i*4 + 1] = f.y;
        ts[r][c0 + i*4 + 2] = f.z;
        ts[r][c0 + i*4 + 3] = f.w;
    }
    __syncthreads();

    const int d  = tid >> 2;
    const int kc = (tid & 3) * 16;
    uint32_t h[8], l[8];
    #pragma unroll
    for (int m = 0; m < 8; m++)
        pack_hl(ts[kc + 2*m][d], ts[kc + 2*m + 1][d], h[m], l[m]);
    const size_t o = (((size_t)bh * DD + d) * SS + n0 + kc) / 2;
    *(uint4*)(g_vth + o)     = make_uint4(h[0], h[4], h[1], h[5]);
    *(uint4*)(g_vth + o + 4) = make_uint4(h[2], h[6], h[3], h[7]);
    *(uint4*)(g_vtl + o)     = make_uint4(l[0], l[4], l[1], l[5]);
    *(uint4*)(g_vtl + o + 4) = make_uint4(l[2], l[6], l[3], l[7]);
}

// ---------------------------------------------------------------------------
// Q fragments (hi/lo), scale*log2e folded in
// ---------------------------------------------------------------------------
__device__ __forceinline__ void load_q_frags(const float* __restrict__ q,
                                             int bh, int r0, int r8, int t,
                                             uint32_t (&qh)[4][4], uint32_t (&ql)[4][4])
{
    const float* qp = q + (size_t)bh * SS * DD;
    const float sc = SCALE * LOG2E;
    #pragma unroll
    for (int ks = 0; ks < 4; ks++) {
        const int c = ks * 16 + t * 2;
        float2 x0 = *(const float2*)(qp + (size_t)r0 * DD + c);
        float2 x1 = *(const float2*)(qp + (size_t)r8 * DD + c);
        float2 x2 = *(const float2*)(qp + (size_t)r0 * DD + c + 8);
        float2 x3 = *(const float2*)(qp + (size_t)r8 * DD + c + 8);
        pack_hl(x0.x * sc, x0.y * sc, qh[ks][0], ql[ks][0]);
        pack_hl(x1.x * sc, x1.y * sc, qh[ks][1], ql[ks][1]);
        pack_hl(x2.x * sc, x2.y * sc, qh[ks][2], ql[ks][2]);
        pack_hl(x3.x * sc, x3.y * sc, qh[ks][3], ql[ks][3]);
    }
}

// ---------------------------------------------------------------------------
// Pass A: QK (bf16x3) -> e = exp(masked score) -> atten (unnormalized), rowsums.
// K tiles double-buffered via cp.async.
// ---------------------------------------------------------------------------
__device__ __forceinline__ void stage_k(uint32_t sbuf, const char* kh_b,
                                        const char* kl_b, int n0, int tid)
{
    #pragma unroll
    for (int cc = 0; cc < 4; cc++) {
        const int c  = tid + cc * 256;          // 0..1023
        const int kr = c >> 3, kc = c & 7;
        const size_t src = (size_t)(n0 + kr) * (DD * 2) + kc * 16;
        const uint32_t dst = kr * 160 + kc * 16;
        CPA16(sbuf + A_KH + dst, kh_b + src);
        CPA16(sbuf + A_KL + dst, kl_b + src);
    }
}

__global__ void __launch_bounds__(256, 2)
sdpa_qk(const float* __restrict__ q, float* __restrict__ atten)
{
    extern __shared__ char smem[];
    const int tid  = threadIdx.x;
    const int lane = tid & 31;
    const int g    = lane >> 2;
    const int t    = lane & 3;
    const int w    = tid >> 5;
    const int bh   = blockIdx.y;
    const int b    = bh / HH;
    const int q0   = blockIdx.x * 128;
    const int r0   = q0 + w * 16 + g;
    const int r8   = r0 + 8;
    const uint32_t sb = smem_u32(smem);

    const size_t mb0 = ((size_t)b * SS + r0) * 64;
    const size_t mb8 = ((size_t)b * SS + r8) * 64;
    float* arow_g  = atten + ((size_t)bh * SS + r0) * SS;
    float* arow_g8 = atten + ((size_t)bh * SS + r8) * SS;

    const char* kh_b = (const char*)g_kh + (size_t)bh * SS * DD * 2;
    const char* kl_b = (const char*)g_kl + (size_t)bh * SS * DD * 2;

    // prologue: stage tile 0; overlap q-fragment conversion with it
    stage_k(sb, kh_b, kl_b, 0, tid);
    CPA_COMMIT();

    uint32_t qh[4][4], ql[4][4];
    load_q_frags(q, bh, r0, r8, t, qh, ql);

    float sum_g = 0.0f, sum_g8 = 0.0f;

    #pragma unroll 1
    for (int kt = 0; kt < 16; kt++) {
        const int n0 = kt * 128;
        const char* bufc = smem + (kt & 1) * A_BUF;

        if (kt + 1 < 16) {
            stage_k(sb + ((kt + 1) & 1) * A_BUF, kh_b, kl_b, (kt + 1) * 128, tid);
            CPA_COMMIT();
            CPA_WAIT(1);
        } else {
            CPA_WAIT(0);
        }
        __syncthreads();

        uint4 mg = *(const uint4*)(g_mbits + mb0 + n0 / 32);
        uint4 m8 = *(const uint4*)(g_mbits + mb8 + n0 / 32);
        const uint32_t* mgw = (const uint32_t*)&mg;
        const uint32_t* m8w = (const uint32_t*)&m8;

        #pragma unroll
        for (int h = 0; h < 2; h++) {
            float s[8][4];
            #pragma unroll
            for (int nt = 0; nt < 8; nt++)
                #pragma unroll
                for (int i = 0; i < 4; i++) s[nt][i] = 0.0f;

            #pragma unroll
            for (int ks = 0; ks < 4; ks++) {
                #pragma unroll
                for (int pass = 0; pass < 3; pass++) {
                    const uint32_t* A = (pass == 2) ? ql[ks] : qh[ks];
                    const int bb = (pass == 1) ? A_KL : A_KH;
                    #pragma unroll
                    for (int nt = 0; nt < 8; nt++) {
                        const char* ad = bufc + bb + ((h * 8 + nt) * 8 + g) * 160
                                       + ks * 32 + t * 8;
                        uint2 b01 = *(const uint2*)ad;   // LDS.64 pairs (p, p+4)
                        MMA(s[nt], A, b01.x, b01.y);
                    }
                }
            }

            #pragma unroll
            for (int nt = 0; nt < 8; nt++) {
                const int ntg = h * 8 + nt;
                const uint32_t wg = mgw[ntg >> 2] >> ((ntg & 3) * 8 + t * 2);
                const uint32_t w8 = m8w[ntg >> 2] >> ((ntg & 3) * 8 + t * 2);
                const float e0 = (wg      & 1) ? 0.0f : ex2(s[nt][0]);
                const float e1 = (wg >> 1 & 1) ? 0.0f : ex2(s[nt][1]);
                const float e2 = (w8      & 1) ? 0.0f : ex2(s[nt][2]);
                const float e3 = (w8 >> 1 & 1) ? 0.0f : ex2(s[nt][3]);
                sum_g  += e0 + e1;
                sum_g8 += e2 + e3;
                const int c = n0 + ntg * 8 + t * 2;
                __stcs((float2*)(arow_g  + c), make_float2(e0, e1));
                __stcs((float2*)(arow_g8 + c), make_float2(e2, e3));
            }
        }
        __syncthreads();   // buf[kt&1] fully read before iter kt+1 restages it
    }

    sum_g  += __shfl_xor_sync(0xffffffffu, sum_g, 1);
    sum_g  += __shfl_xor_sync(0xffffffffu, sum_g, 2);
    sum_g8 += __shfl_xor_sync(0xffffffffu, sum_g8, 1);
    sum_g8 += __shfl_xor_sync(0xffffffffu, sum_g8, 2);
    if (t == 0) {
        g_row_s[bh * SS + r0] = sum_g;
        g_row_s[bh * SS + r8] = sum_g8;
    }
}

// ---------------------------------------------------------------------------
// Pass B: p = e/sum -> atten (final), out = P V. V tiles double-buffered.
// ---------------------------------------------------------------------------
__device__ __forceinline__ void stage_v(uint32_t sbuf, const char* vh_b,
                                        const char* vl_b, int n0, int tid)
{
    #pragma unroll
    for (int cc = 0; cc < 4; cc++) {
        const int c  = tid + cc * 256;          // 0..1023
        const int vd = c >> 4, vc = c & 15;
        const size_t src = ((size_t)vd * SS + n0) * 2 + vc * 16;
        const uint32_t dst = vd * 288 + vc * 16;
        CPA16(sbuf + B_VH + dst, vh_b + src);
        CPA16(sbuf + B_VL + dst, vl_b + src);
    }
}

__global__ void __launch_bounds__(256, 2)
sdpa_av(float* __restrict__ atten, float* __restrict__ out)
{
    extern __shared__ char smem[];
    const int tid  = threadIdx.x;
    const int lane = tid & 31;
    const int g    = lane >> 2;
    const int t    = lane & 3;
    const int w    = tid >> 5;
    const int bh   = blockIdx.y;
    const int q0   = blockIdx.x * 128;
    const int r0   = q0 + w * 16 + g;
    const int r8   = r0 + 8;
    const uint32_t sb = smem_u32(smem);

    float* arow_g  = atten + ((size_t)bh * SS + r0) * SS;
    float* arow_g8 = atten + ((size_t)bh * SS + r8) * SS;

    const char* vh_b = (const char*)g_vth + (size_t)bh * SS * DD * 2;
    const char* vl_b = (const char*)g_vtl + (size_t)bh * SS * DD * 2;

    stage_v(sb, vh_b, vl_b, 0, tid);
    CPA_COMMIT();

    const float inv_g  = 1.0f / g_row_s[bh * SS + r0];
    const float inv_g8 = 1.0f / g_row_s[bh * SS + r8];

    float o[8][4];
    #pragma unroll
    for (int nd = 0; nd < 8; nd++)
        #pragma unroll
        for (int i = 0; i < 4; i++) o[nd][i] = 0.0f;

    #pragma unroll 1
    for (int kt = 0; kt < 16; kt++) {
        const int n0 = kt * 128;
        const char* bufc = smem + (kt & 1) * B_BUF;

        if (kt + 1 < 16) {
            stage_v(sb + ((kt + 1) & 1) * B_BUF, vh_b, vl_b, (kt + 1) * 128, tid);
            CPA_COMMIT();
            CPA_WAIT(1);
        } else {
            CPA_WAIT(0);
        }
        __syncthreads();

        #pragma unroll
        for (int h = 0; h < 2; h++) {
            // load this half's e values (independent streaming loads)
            float2 eg[8], e8[8];
            #pragma unroll
            for (int nt = 0; nt < 8; nt++) {
                const int c = n0 + (h * 8 + nt) * 8 + t * 2;
                eg[nt] = __ldcs((const float2*)(arow_g  + c));
                e8[nt] = __ldcs((const float2*)(arow_g8 + c));
            }

            #pragma unroll
            for (int kap = 0; kap < 4; kap++) {
                uint32_t ah[4], al[4];
                #pragma unroll
                for (int i = 0; i < 2; i++) {
                    const int nt = kap * 2 + i;
                    const float p0 = eg[nt].x * inv_g;
                    const float p1 = eg[nt].y * inv_g;
                    const float p2 = e8[nt].x * inv_g8;
                    const float p3 = e8[nt].y * inv_g8;
                    const int c = n0 + (h * 8 + nt) * 8 + t * 2;
                    __stcs((float2*)(arow_g  + c), make_float2(p0, p1));
                    __stcs((float2*)(arow_g8 + c), make_float2(p2, p3));
                    pack_hl(p0, p1, ah[i*2+0], al[i*2+0]);
                    pack_hl(p2, p3, ah[i*2+1], al[i*2+1]);
                }
                #pragma unroll
                for (int nd = 0; nd < 8; nd++) {
                    const int vbase = (nd * 8 + g) * 288 + (h * 4 + kap) * 32 + t * 8;
                    uint2 vh2 = *(const uint2*)(bufc + B_VH + vbase);
                    uint2 vl2 = *(const uint2*)(bufc + B_VL + vbase);
                    MMA(o[nd], ah, vh2.x, vh2.y);
                    MMA(o[nd], ah, vl2.x, vl2.y);
                    MMA(o[nd], al, vh2.x, vh2.y);
                }
            }
        }
        __syncthreads();   // buf[kt&1] fully read before iter kt+1 restages it
    }

    float* orow_g  = out + ((size_t)bh * SS + r0) * DD;
    float* orow_g8 = out + ((size_t)bh * SS + r8) * DD;
    #pragma unroll
    for (int nd = 0; nd < 8; nd++) {
        *(float2*)(orow_g  + nd * 8 + t * 2) = make_float2(o[nd][0], o[nd][1]);
        *(float2*)(orow_g8 + nd * 8 + t * 2) = make_float2(o[nd][2], o[nd][3]);
    }
}

// ---------------------------------------------------------------------------
extern "C" void kernel_launch(void* const* d_in, const int* in_sizes, int n_in,
                              void* d_out, int out_size)
{
    const float* q = (const float*)d_in[0];
    const float* k = (const float*)d_in[1];
    const float* v = (const float*)d_in[2];
    const int*   mask = (const int*)d_in[3];

    float* out   = (float*)d_out;                 // [B,H,S,D]
    float* atten = out + (size_t)BH * SS * DD;    // [B,H,S,S]

    cudaFuncSetAttribute(sdpa_qk, cudaFuncAttributeMaxDynamicSharedMemorySize, SMEM_A);
    cudaFuncSetAttribute(sdpa_av, cudaFuncAttributeMaxDynamicSharedMemorySize, SMEM_B);

    mask_pack<<<1024, 256>>>(mask);
    conv_k<<<BH * SS * DD / (256 * 16), 256>>>(k);
    conv_vt<<<dim3(SS / 64, BH), 256>>>(v);
    dim3 grid(SS / 128, BH);
    sdpa_qk<<<grid, 256, SMEM_A>>>(q, atten);
    sdpa_av<<<grid, 256, SMEM_B>>>(atten, out);
    (void)in_sizes; (void)n_in; (void)out_size;
}